// round 15
// baseline (speedup 1.0000x reference)
#include <cuda_runtime.h>
#include <cuda_fp16.h>
#include <math.h>
#include <stdint.h>

// ---------------------------------------------------------------------------
// Problem constants
// ---------------------------------------------------------------------------
static constexpr int BATCH = 4;
static constexpr int NSEQ  = 4096;
static constexpr int DIMC  = 768;       // input dim == head dim
static constexpr int H3    = 3 * DIMC;  // 2304

// Scratch
__device__ __half g_xh[(size_t)BATCH * NSEQ * DIMC];          // 25 MB
__device__ __half g_qkvh[(size_t)BATCH * NSEQ * H3];          // 75 MB
__device__ __half g_E[(size_t)BATCH * NSEQ * NSEQ];           // 134 MB (exp(scores), unnormalized)
__device__ float  g_sums[(size_t)BATCH * NSEQ];               // 64 KB  (rowsum of E, via atomics)
__device__ __half g_Wth[(size_t)H3 * DIMC];                   // 3.5 MB
__device__ __half g_Vth[(size_t)BATCH * DIMC * NSEQ];         // 25 MB

// ---------------------------------------------------------------------------
// Helpers
// ---------------------------------------------------------------------------
__device__ __forceinline__ uint32_t smem_to_u32(const void* p) {
    uint32_t a;
    asm("{ .reg .u64 t; cvta.to.shared.u64 t, %1; cvt.u32.u64 %0, t; }"
        : "=r"(a) : "l"(p));
    return a;
}

__device__ __forceinline__ void cp_async16(uint32_t smem_addr, const void* gptr) {
    asm volatile("cp.async.cg.shared.global [%0], [%1], 16;"
                 :: "r"(smem_addr), "l"(gptr));
}

#define LDSM_X4(r, addr) \
    asm volatile("ldmatrix.sync.aligned.m8n8.x4.shared.b16 {%0,%1,%2,%3}, [%4];" \
                 : "=r"((r)[0]), "=r"((r)[1]), "=r"((r)[2]), "=r"((r)[3]) : "r"(addr))

__device__ __forceinline__ void mma_f16(float* d, const uint32_t* a, const uint32_t* b) {
    asm volatile(
        "mma.sync.aligned.m16n8k16.row.col.f32.f16.f16.f32 "
        "{%0,%1,%2,%3}, {%4,%5,%6,%7}, {%8,%9}, {%0,%1,%2,%3};"
        : "+f"(d[0]), "+f"(d[1]), "+f"(d[2]), "+f"(d[3])
        : "r"(a[0]), "r"(a[1]), "r"(a[2]), "r"(a[3]), "r"(b[0]), "r"(b[1]));
}

__device__ __forceinline__ float ex2f(float t) {
    float r;
    asm("ex2.approx.f32 %0, %1;" : "=f"(r) : "f"(t));
    return r;
}

// Epilogue modes
static constexpr int EPI_BIAS_HALF = 0;   // += bias[N], write fp16 (QKV)
static constexpr int EPI_EXP_HALF  = 1;   // exp2(v*alpha - SHIFT) fp16 + atomic rowsum (S->E)
static constexpr int EPI_SCALE_F32 = 2;   // *= 1/sums[row], write fp32 (PV)

static constexpr float EXP_SHIFT_L2 = 2.8853900817779268f;   // 2 * log2(e)

// ---------------------------------------------------------------------------
// fp16 mma.sync NT GEMM: C[M,N] = f( A[M,K] @ B[N,K]^T )
// A, B fp16 K-major. Block tile 128x128x32, 128 threads (4 warps as 2x2,
// warp tile 64x64), 4-stage cp.async pipeline, 2 CTAs/SM.
// Software-pipelined fragments: ks1 LDSM latency hidden under ks0 MMAs
// (needs ~210 regs -> launch_bounds(128,2)).
// Smem row 40 halfs (80B, conflict-free for cp.async and ldmatrix).
// fp32 accumulate. Grid: (N/128, M/128, batch).
// ---------------------------------------------------------------------------
static constexpr int STAGES = 4;
static constexpr int SROWH = 40;                         // halfs per smem row
static constexpr int T_STAGE_BYTES = 128 * SROWH * 2;    // 10240 (each of A and B)
static constexpr uint32_t GEMM_DYNSMEM =
    STAGES * 2u * (uint32_t)T_STAGE_BYTES;               // 81920

// Staged-epilogue tile: 128 rows x 136 halfs (272B rows, bank-shift 4/row)
static constexpr int EROWH = 136;

template <int EPI>
__global__ __launch_bounds__(128, 2)
void hgemm_nt(const __half* __restrict__ A, const __half* __restrict__ B,
              const float* __restrict__ extra, float* __restrict__ sums,
              void* __restrict__ Cout,
              int K, int lda, int ldb, int ldc,
              size_t sA, size_t sB, size_t sC, float alpha)
{
    extern __shared__ __half hsmem[];

    const int tid = threadIdx.x;
    const int lane = tid & 31;
    const int wid = tid >> 5;
    const int warp_m = wid & 1;       // 0..1  (64-row slab)
    const int warp_n = wid >> 1;      // 0..1  (64-col slab)
    const int bm = blockIdx.y * 128;
    const int bn = blockIdx.x * 128;

    const __half* Abase = A + blockIdx.z * sA + (size_t)bm * lda;
    const __half* Bbase = B + blockIdx.z * sB + (size_t)bn * ldb;

    const uint32_t smemA_u = smem_to_u32(hsmem);
    const uint32_t smemB_u = smemA_u + STAGES * T_STAGE_BYTES;

    const int niter = K >> 5;

    // Producer: per stage A = 512 16B-chunks (4/thread), B = 512 (4/thread)
    auto issue = [&](int it) {
        if (it < niter) {
            const int s = it & (STAGES - 1);
            const uint32_t dA = smemA_u + s * T_STAGE_BYTES;
            const uint32_t dB = smemB_u + s * T_STAGE_BYTES;
            const int kofs = it * 32;
#pragma unroll
            for (int p = 0; p < 4; p++) {
                const int c = tid + 128 * p;
                const int r = c >> 2, sub = c & 3;
                cp_async16(dA + (uint32_t)(r * 80 + sub * 16),
                           Abase + (size_t)r * lda + kofs + sub * 8);
                cp_async16(dB + (uint32_t)(r * 80 + sub * 16),
                           Bbase + (size_t)r * ldb + kofs + sub * 8);
            }
        }
        asm volatile("cp.async.commit_group;" ::: "memory");
    };

    issue(0); issue(1); issue(2);

    float acc[4][8][4];
#pragma unroll
    for (int mi = 0; mi < 4; mi++)
#pragma unroll
        for (int ni = 0; ni < 8; ni++)
#pragma unroll
            for (int j = 0; j < 4; j++) acc[mi][ni][j] = 0.0f;

    // ldmatrix per-lane base byte offsets (within a stage), k-step 0
    const int laneM = lane >> 3;      // matrix id 0..3
    const int laneR = lane & 7;
    uint32_t aoff[4], boff[4];
#pragma unroll
    for (int mi = 0; mi < 4; mi++) {
        const int row = warp_m * 64 + mi * 16 + (laneM & 1) * 8 + laneR;
        aoff[mi] = (uint32_t)(row * SROWH + (laneM >> 1) * 8) * 2u;
    }
#pragma unroll
    for (int pi = 0; pi < 4; pi++) {
        const int row = warp_n * 64 + pi * 16 + (laneM >> 1) * 8 + laneR;
        boff[pi] = (uint32_t)(row * SROWH + (laneM & 1) * 8) * 2u;
    }

    uint32_t afr[2][4][4];
    uint32_t bfr[2][4][4];   // [ks][pair][4]; pair pi holds frags of n-tiles 2pi, 2pi+1

    for (int it = 0; it < niter; ++it) {
        asm volatile("cp.async.wait_group 2;" ::: "memory");
        __syncthreads();

        const int s = it & (STAGES - 1);
        const uint32_t sAu = smemA_u + s * T_STAGE_BYTES;
        const uint32_t sBu = smemB_u + s * T_STAGE_BYTES;

        // ks0 fragment loads
#pragma unroll
        for (int mi = 0; mi < 4; mi++) LDSM_X4(afr[0][mi], sAu + aoff[mi]);
#pragma unroll
        for (int pi = 0; pi < 4; pi++) LDSM_X4(bfr[0][pi], sBu + boff[pi]);

        // next-stage cp.async (independent of LDSM results)
        issue(it + 3);

        // ks1 fragment loads — latency hidden under ks0 MMAs below
#pragma unroll
        for (int mi = 0; mi < 4; mi++) LDSM_X4(afr[1][mi], sAu + aoff[mi] + 32);
#pragma unroll
        for (int pi = 0; pi < 4; pi++) LDSM_X4(bfr[1][pi], sBu + boff[pi] + 32);

#pragma unroll
        for (int ks = 0; ks < 2; ks++)
#pragma unroll
            for (int mi = 0; mi < 4; mi++)
#pragma unroll
                for (int ni = 0; ni < 8; ni++)
                    mma_f16(acc[mi][ni], afr[ks][mi], &bfr[ks][ni >> 1][(ni & 1) * 2]);
    }

    // ---------------- Epilogue ----------------
    const int rrow = warp_m * 64 + (lane >> 2);           // row within tile
    const int rcol = warp_n * 64 + (lane & 3) * 2;        // col within tile

    if (EPI == EPI_EXP_HALF) {
        // exp2(v*alpha - SHIFT) -> fp16, staged via smem, coalesced 16B stores.
        // Row sums accumulated in-register and atomically added to sums[].
        __syncthreads();                                   // all LDSM done; reuse smem
        float* bsums = sums + (size_t)blockIdx.z * NSEQ + bm;
#pragma unroll
        for (int mi = 0; mi < 4; mi++) {
            float rs0 = 0.0f, rs1 = 0.0f;                  // rows rrow+mi*16, +8
#pragma unroll
            for (int ni = 0; ni < 8; ni++) {
                const int r0 = rrow + mi * 16;
                const int c  = rcol + ni * 8;
                float e0 = ex2f(fmaf(acc[mi][ni][0], alpha, -EXP_SHIFT_L2));
                float e1 = ex2f(fmaf(acc[mi][ni][1], alpha, -EXP_SHIFT_L2));
                float e2 = ex2f(fmaf(acc[mi][ni][2], alpha, -EXP_SHIFT_L2));
                float e3 = ex2f(fmaf(acc[mi][ni][3], alpha, -EXP_SHIFT_L2));
                rs0 += e0 + e1;
                rs1 += e2 + e3;
                *(__half2*)(hsmem + r0 * EROWH + c)       = __floats2half2_rn(e0, e1);
                *(__half2*)(hsmem + (r0 + 8) * EROWH + c) = __floats2half2_rn(e2, e3);
            }
            // reduce over the 4-lane quad (cols) -> lane with (lane&3)==0 holds row sum
            rs0 += __shfl_xor_sync(0xFFFFFFFFu, rs0, 1);
            rs0 += __shfl_xor_sync(0xFFFFFFFFu, rs0, 2);
            rs1 += __shfl_xor_sync(0xFFFFFFFFu, rs1, 1);
            rs1 += __shfl_xor_sync(0xFFFFFFFFu, rs1, 2);
            if ((lane & 3) == 0) {
                atomicAdd(bsums + rrow + mi * 16, rs0);
                atomicAdd(bsums + rrow + mi * 16 + 8, rs1);
            }
        }
        __syncthreads();
        __half* C = (__half*)Cout + blockIdx.z * sC;
#pragma unroll
        for (int i = 0; i < 16; i++) {
            const int idx = i * 128 + tid;
            const int r = idx >> 4;          // 0..127
            const int ch = idx & 15;         // 16B chunk
            uint4 val = *(const uint4*)(hsmem + r * EROWH + ch * 8);
            *(uint4*)(C + (size_t)(bm + r) * ldc + bn + ch * 8) = val;
        }
        return;
    }

    const int erow = bm + rrow;
    const int ecol = bn + rcol;
#pragma unroll
    for (int mi = 0; mi < 4; mi++) {
        float s0 = 1.0f, s1 = 1.0f;
        if (EPI == EPI_SCALE_F32) {
            const float* bsums = sums + (size_t)blockIdx.z * NSEQ;
            s0 = __fdividef(1.0f, bsums[erow + mi * 16]);
            s1 = __fdividef(1.0f, bsums[erow + mi * 16 + 8]);
        }
#pragma unroll
        for (int ni = 0; ni < 8; ni++) {
            const int m0 = erow + mi * 16;
            const int n0 = ecol + ni * 8;
            float v0 = acc[mi][ni][0];
            float v1 = acc[mi][ni][1];
            float v2 = acc[mi][ni][2];
            float v3 = acc[mi][ni][3];
            if (EPI == EPI_BIAS_HALF) {
                const float b0 = extra[n0], b1 = extra[n0 + 1];
                v0 += b0; v1 += b1; v2 += b0; v3 += b1;
                __half* C = (__half*)Cout + blockIdx.z * sC;
                *(__half2*)(C + (size_t)m0 * ldc + n0)       = __floats2half2_rn(v0, v1);
                *(__half2*)(C + (size_t)(m0 + 8) * ldc + n0) = __floats2half2_rn(v2, v3);
            } else {  // EPI_SCALE_F32
                float* C = (float*)Cout + blockIdx.z * sC;
                *(float2*)(C + (size_t)m0 * ldc + n0)       = make_float2(v0 * s0, v1 * s0);
                *(float2*)(C + (size_t)(m0 + 8) * ldc + n0) = make_float2(v2 * s1, v3 * s1);
            }
        }
    }
}

// ---------------------------------------------------------------------------
// fp32 -> fp16 copy
// ---------------------------------------------------------------------------
__global__ __launch_bounds__(256)
void f2h_kernel(const float* __restrict__ src, __half* __restrict__ dst, size_t n4)
{
    const size_t stride = (size_t)gridDim.x * 256;
    for (size_t i = blockIdx.x * 256ull + threadIdx.x; i < n4; i += stride) {
        float4 v = ((const float4*)src)[i];
        ((__half2*)dst)[2 * i]     = __floats2half2_rn(v.x, v.y);
        ((__half2*)dst)[2 * i + 1] = __floats2half2_rn(v.z, v.w);
    }
}

// ---------------------------------------------------------------------------
// Zero the rowsum accumulators (re-run on every graph replay).
// ---------------------------------------------------------------------------
__global__ __launch_bounds__(256)
void zero_sums_kernel(float* __restrict__ sums)
{
    const int i = blockIdx.x * 256 + threadIdx.x;
    if (i < BATCH * NSEQ) sums[i] = 0.0f;
}

// ---------------------------------------------------------------------------
// Tiled transpose with dtype conversion: out[c, r] = in[r, c]
// ---------------------------------------------------------------------------
template <typename TIN, typename TOUT>
__global__ __launch_bounds__(256)
void transpose_t(const TIN* __restrict__ in, TOUT* __restrict__ out,
                 int ld_in, int ld_out, size_t sIn, size_t sOut)
{
    __shared__ float tile[32][33];
    in  += blockIdx.z * sIn;
    out += blockIdx.z * sOut;
    const int r0 = blockIdx.y * 32;
    const int c0 = blockIdx.x * 32;
    const int tx = threadIdx.x;
    const int ty = threadIdx.y;
#pragma unroll
    for (int i = 0; i < 32; i += 8)
        tile[ty + i][tx] = (float)in[(size_t)(r0 + ty + i) * ld_in + c0 + tx];
    __syncthreads();
#pragma unroll
    for (int i = 0; i < 32; i += 8)
        out[(size_t)(c0 + ty + i) * ld_out + r0 + tx] = (TOUT)tile[tx][ty + i];
}

// ---------------------------------------------------------------------------
extern "C" void kernel_launch(void* const* d_in, const int* in_sizes, int n_in,
                              void* d_out, int out_size)
{
    const float* x = (const float*)d_in[0];   // [4, 4096, 768]
    const float* W = (const float*)d_in[1];   // [768, 2304]
    const float* b = (const float*)d_in[2];   // [2304]
    float* out = (float*)d_out;               // [4, 4096, 768]

    __half *xh, *qkvh, *E, *Wth, *Vth;
    float *sums;
    cudaGetSymbolAddress((void**)&xh, g_xh);
    cudaGetSymbolAddress((void**)&qkvh, g_qkvh);
    cudaGetSymbolAddress((void**)&E, g_E);
    cudaGetSymbolAddress((void**)&sums, g_sums);
    cudaGetSymbolAddress((void**)&Wth, g_Wth);
    cudaGetSymbolAddress((void**)&Vth, g_Vth);

    cudaFuncSetAttribute(hgemm_nt<EPI_BIAS_HALF>, cudaFuncAttributeMaxDynamicSharedMemorySize, GEMM_DYNSMEM);
    cudaFuncSetAttribute(hgemm_nt<EPI_EXP_HALF>,  cudaFuncAttributeMaxDynamicSharedMemorySize, GEMM_DYNSMEM);
    cudaFuncSetAttribute(hgemm_nt<EPI_SCALE_F32>, cudaFuncAttributeMaxDynamicSharedMemorySize, GEMM_DYNSMEM);

    const size_t qkvStride = (size_t)NSEQ * H3;
    const size_t sStride   = (size_t)NSEQ * NSEQ;
    const size_t oStride   = (size_t)NSEQ * DIMC;
    const size_t vtStride  = (size_t)DIMC * NSEQ;

    // 0a) xh = fp16(x);  0b) zero rowsum accumulators
    f2h_kernel<<<2048, 256>>>(x, xh, (size_t)BATCH * NSEQ * DIMC / 4);
    zero_sums_kernel<<<(BATCH * NSEQ + 255) / 256, 256>>>(sums);

    // 0c) Wth = fp16(W^T) : [768,2304] -> [2304,768]
    {
        dim3 grid(H3 / 32, DIMC / 32, 1);
        transpose_t<float, __half><<<grid, dim3(32, 8)>>>(W, Wth, H3, DIMC, 0, 0);
    }

    // 1) qkvh = fp16(xh @ Wth^T + b) : M=16384, N=2304, K=768
    {
        dim3 grid(H3 / 128, (BATCH * NSEQ) / 128, 1);
        hgemm_nt<EPI_BIAS_HALF><<<grid, 128, GEMM_DYNSMEM>>>(
            xh, Wth, b, nullptr, qkvh, DIMC, DIMC, DIMC, H3, 0, 0, 0, 1.0f);
    }

    // 2) Vth = V^T per batch : [4096,768] -> [768,4096]
    {
        dim3 grid(DIMC / 32, NSEQ / 32, BATCH);
        transpose_t<__half, __half><<<grid, dim3(32, 8)>>>(qkvh + 2 * DIMC, Vth, H3, NSEQ,
                                                           qkvStride, vtStride);
    }

    // 3) E = exp(Q @ K^T / sqrt(768) - 2) per batch (fp16 out) + atomic rowsums
    {
        dim3 grid(NSEQ / 128, NSEQ / 128, BATCH);
        const float alpha = 1.4426950408889634f / sqrtf((float)DIMC);  // log2(e)/sqrt(H)
        hgemm_nt<EPI_EXP_HALF><<<grid, 128, GEMM_DYNSMEM>>>(
            qkvh, qkvh + DIMC, nullptr, sums, E, DIMC, H3, H3, NSEQ,
            qkvStride, qkvStride, sStride, alpha);
    }

    // 4) out = diag(1/sums) * (E @ Vth^T) per batch (fp32 out) : M=4096, N=768, K=4096
    {
        dim3 grid(DIMC / 128, NSEQ / 128, BATCH);
        hgemm_nt<EPI_SCALE_F32><<<grid, 128, GEMM_DYNSMEM>>>(
            E, Vth, nullptr, sums, out, NSEQ, NSEQ, NSEQ, DIMC,
            sStride, vtStride, oStride, 1.0f);
    }
}

// round 16
// speedup vs baseline: 1.0494x; 1.0494x over previous
#include <cuda_runtime.h>
#include <cuda_fp16.h>
#include <math.h>
#include <stdint.h>

// ---------------------------------------------------------------------------
// Problem constants
// ---------------------------------------------------------------------------
static constexpr int BATCH = 4;
static constexpr int NSEQ  = 4096;
static constexpr int DIMC  = 768;       // input dim == head dim
static constexpr int H3    = 3 * DIMC;  // 2304

// Scratch
__device__ __half g_xh[(size_t)BATCH * NSEQ * DIMC];          // 25 MB
__device__ __half g_qkvh[(size_t)BATCH * NSEQ * H3];          // 75 MB
__device__ __half g_E[(size_t)BATCH * NSEQ * NSEQ];           // 134 MB (exp(scores), unnormalized)
__device__ float  g_sums[(size_t)BATCH * NSEQ];               // 64 KB  (rowsum of E, via atomics)
__device__ __half g_Wth[(size_t)H3 * DIMC];                   // 3.5 MB
__device__ __half g_Vth[(size_t)BATCH * DIMC * NSEQ];         // 25 MB

// ---------------------------------------------------------------------------
// Helpers
// ---------------------------------------------------------------------------
__device__ __forceinline__ uint32_t smem_to_u32(const void* p) {
    uint32_t a;
    asm("{ .reg .u64 t; cvta.to.shared.u64 t, %1; cvt.u32.u64 %0, t; }"
        : "=r"(a) : "l"(p));
    return a;
}

__device__ __forceinline__ void cp_async16(uint32_t smem_addr, const void* gptr) {
    asm volatile("cp.async.cg.shared.global [%0], [%1], 16;"
                 :: "r"(smem_addr), "l"(gptr));
}

#define LDSM_X4(r, addr) \
    asm volatile("ldmatrix.sync.aligned.m8n8.x4.shared.b16 {%0,%1,%2,%3}, [%4];" \
                 : "=r"((r)[0]), "=r"((r)[1]), "=r"((r)[2]), "=r"((r)[3]) : "r"(addr))

__device__ __forceinline__ void mma_f16(float* d, const uint32_t* a, const uint32_t* b) {
    asm volatile(
        "mma.sync.aligned.m16n8k16.row.col.f32.f16.f16.f32 "
        "{%0,%1,%2,%3}, {%4,%5,%6,%7}, {%8,%9}, {%0,%1,%2,%3};"
        : "+f"(d[0]), "+f"(d[1]), "+f"(d[2]), "+f"(d[3])
        : "r"(a[0]), "r"(a[1]), "r"(a[2]), "r"(a[3]), "r"(b[0]), "r"(b[1]));
}

// fp16-accumulator variant: D/C are 2 x f16x2 regs — runs at 2x the f32-accum rate
__device__ __forceinline__ void mma_f16acc(uint32_t* d, const uint32_t* a, const uint32_t* b) {
    asm volatile(
        "mma.sync.aligned.m16n8k16.row.col.f16.f16.f16.f16 "
        "{%0,%1}, {%2,%3,%4,%5}, {%6,%7}, {%0,%1};"
        : "+r"(d[0]), "+r"(d[1])
        : "r"(a[0]), "r"(a[1]), "r"(a[2]), "r"(a[3]), "r"(b[0]), "r"(b[1]));
}

__device__ __forceinline__ float ex2f(float t) {
    float r;
    asm("ex2.approx.f32 %0, %1;" : "=f"(r) : "f"(t));
    return r;
}

// Epilogue modes
static constexpr int EPI_BIAS_HALF = 0;   // += bias[N], write fp16 (QKV)
static constexpr int EPI_SCALE_F32 = 2;   // *= 1/sums[row], write fp32 (PV)

static constexpr float EXP_SHIFT_L2 = 2.8853900817779268f;   // 2 * log2(e)

// ---------------------------------------------------------------------------
// Shared tiling constants: block tile 128x128x32, 128 threads (4 warps 2x2,
// warp tile 64x64). Smem row 40 halfs (80B, conflict-free).
// ---------------------------------------------------------------------------
static constexpr int STAGES = 3;
static constexpr int SROWH = 40;                         // halfs per smem row
static constexpr int T_STAGE_BYTES = 128 * SROWH * 2;    // 10240 (each of A and B)
static constexpr uint32_t GEMM_DYNSMEM =
    STAGES * 2u * (uint32_t)T_STAGE_BYTES;               // 61440

// Staged-epilogue tile: 128 rows x 136 halfs (272B rows, bank-shift 4/row)
static constexpr int EROWH = 136;

// ---------------------------------------------------------------------------
// f32-accum NT GEMM (QKV / PV): C[M,N] = f( A @ B^T ). 3-stage, 3 CTAs/SM.
// Round-14 structure (best known for f32-accum).
// ---------------------------------------------------------------------------
template <int EPI>
__global__ __launch_bounds__(128, 3)
void hgemm_nt(const __half* __restrict__ A, const __half* __restrict__ B,
              const float* __restrict__ extra, float* __restrict__ sums,
              void* __restrict__ Cout,
              int K, int lda, int ldb, int ldc,
              size_t sA, size_t sB, size_t sC, float alpha)
{
    extern __shared__ __half hsmem[];

    const int tid = threadIdx.x;
    const int lane = tid & 31;
    const int wid = tid >> 5;
    const int warp_m = wid & 1;
    const int warp_n = wid >> 1;
    const int bm = blockIdx.y * 128;
    const int bn = blockIdx.x * 128;

    const __half* Abase = A + blockIdx.z * sA + (size_t)bm * lda;
    const __half* Bbase = B + blockIdx.z * sB + (size_t)bn * ldb;

    const uint32_t smemA_u = smem_to_u32(hsmem);
    const uint32_t smemB_u = smemA_u + STAGES * T_STAGE_BYTES;

    const int niter = K >> 5;

    auto issue = [&](int it) {
        if (it < niter) {
            const int s = it % STAGES;
            const uint32_t dA = smemA_u + s * T_STAGE_BYTES;
            const uint32_t dB = smemB_u + s * T_STAGE_BYTES;
            const int kofs = it * 32;
#pragma unroll
            for (int p = 0; p < 4; p++) {
                const int c = tid + 128 * p;
                const int r = c >> 2, sub = c & 3;
                cp_async16(dA + (uint32_t)(r * 80 + sub * 16),
                           Abase + (size_t)r * lda + kofs + sub * 8);
                cp_async16(dB + (uint32_t)(r * 80 + sub * 16),
                           Bbase + (size_t)r * ldb + kofs + sub * 8);
            }
        }
        asm volatile("cp.async.commit_group;" ::: "memory");
    };

    issue(0); issue(1);

    float acc[4][8][4];
#pragma unroll
    for (int mi = 0; mi < 4; mi++)
#pragma unroll
        for (int ni = 0; ni < 8; ni++)
#pragma unroll
            for (int j = 0; j < 4; j++) acc[mi][ni][j] = 0.0f;

    const int laneM = lane >> 3;
    const int laneR = lane & 7;
    uint32_t aoff[4], boff[4];
#pragma unroll
    for (int mi = 0; mi < 4; mi++) {
        const int row = warp_m * 64 + mi * 16 + (laneM & 1) * 8 + laneR;
        aoff[mi] = (uint32_t)(row * SROWH + (laneM >> 1) * 8) * 2u;
    }
#pragma unroll
    for (int pi = 0; pi < 4; pi++) {
        const int row = warp_n * 64 + pi * 16 + (laneM >> 1) * 8 + laneR;
        boff[pi] = (uint32_t)(row * SROWH + (laneM & 1) * 8) * 2u;
    }

    for (int it = 0; it < niter; ++it) {
        asm volatile("cp.async.wait_group 1;" ::: "memory");
        __syncthreads();
        issue(it + 2);

        const int s = it % STAGES;
        const uint32_t sAu = smemA_u + s * T_STAGE_BYTES;
        const uint32_t sBu = smemB_u + s * T_STAGE_BYTES;

#pragma unroll
        for (int ks = 0; ks < 2; ks++) {
            uint32_t afr[4][4];
            uint32_t bfr[4][4];
#pragma unroll
            for (int mi = 0; mi < 4; mi++) LDSM_X4(afr[mi], sAu + aoff[mi] + ks * 32);
#pragma unroll
            for (int pi = 0; pi < 4; pi++) LDSM_X4(bfr[pi], sBu + boff[pi] + ks * 32);
#pragma unroll
            for (int mi = 0; mi < 4; mi++)
#pragma unroll
                for (int ni = 0; ni < 8; ni++)
                    mma_f16(acc[mi][ni], afr[mi], &bfr[ni >> 1][(ni & 1) * 2]);
        }
    }

    // Epilogue
    const int rrow = warp_m * 64 + (lane >> 2);
    const int rcol = warp_n * 64 + (lane & 3) * 2;
    const int erow = bm + rrow;
    const int ecol = bn + rcol;
#pragma unroll
    for (int mi = 0; mi < 4; mi++) {
        float s0 = 1.0f, s1 = 1.0f;
        if (EPI == EPI_SCALE_F32) {
            const float* bsums = sums + (size_t)blockIdx.z * NSEQ;
            s0 = __fdividef(1.0f, bsums[erow + mi * 16]);
            s1 = __fdividef(1.0f, bsums[erow + mi * 16 + 8]);
        }
#pragma unroll
        for (int ni = 0; ni < 8; ni++) {
            const int m0 = erow + mi * 16;
            const int n0 = ecol + ni * 8;
            float v0 = acc[mi][ni][0];
            float v1 = acc[mi][ni][1];
            float v2 = acc[mi][ni][2];
            float v3 = acc[mi][ni][3];
            if (EPI == EPI_BIAS_HALF) {
                const float b0 = extra[n0], b1 = extra[n0 + 1];
                v0 += b0; v1 += b1; v2 += b0; v3 += b1;
                __half* C = (__half*)Cout + blockIdx.z * sC;
                *(__half2*)(C + (size_t)m0 * ldc + n0)       = __floats2half2_rn(v0, v1);
                *(__half2*)(C + (size_t)(m0 + 8) * ldc + n0) = __floats2half2_rn(v2, v3);
            } else {  // EPI_SCALE_F32
                float* C = (float*)Cout + blockIdx.z * sC;
                *(float2*)(C + (size_t)m0 * ldc + n0)       = make_float2(v0 * s0, v1 * s0);
                *(float2*)(C + (size_t)(m0 + 8) * ldc + n0) = make_float2(v2 * s1, v3 * s1);
            }
        }
    }
}

// ---------------------------------------------------------------------------
// fp16-accum NT GEMM for E = exp(scores): C fp16, frag-pipelined, 3 CTAs/SM.
// acc regs halved (64) -> room for double-buffered fragments at occ 3.
// Epilogue: exp2(v*alpha - SHIFT) -> fp16 staged via smem + atomic rowsums.
// ---------------------------------------------------------------------------
__global__ __launch_bounds__(128, 3)
void hgemm_exp(const __half* __restrict__ A, const __half* __restrict__ B,
               float* __restrict__ sums, __half* __restrict__ Cout,
               int K, int lda, int ldb, int ldc,
               size_t sA, size_t sB, size_t sC, float alpha)
{
    extern __shared__ __half hsmem[];

    const int tid = threadIdx.x;
    const int lane = tid & 31;
    const int wid = tid >> 5;
    const int warp_m = wid & 1;
    const int warp_n = wid >> 1;
    const int bm = blockIdx.y * 128;
    const int bn = blockIdx.x * 128;

    const __half* Abase = A + blockIdx.z * sA + (size_t)bm * lda;
    const __half* Bbase = B + blockIdx.z * sB + (size_t)bn * ldb;

    const uint32_t smemA_u = smem_to_u32(hsmem);
    const uint32_t smemB_u = smemA_u + STAGES * T_STAGE_BYTES;

    const int niter = K >> 5;

    auto issue = [&](int it) {
        if (it < niter) {
            const int s = it % STAGES;
            const uint32_t dA = smemA_u + s * T_STAGE_BYTES;
            const uint32_t dB = smemB_u + s * T_STAGE_BYTES;
            const int kofs = it * 32;
#pragma unroll
            for (int p = 0; p < 4; p++) {
                const int c = tid + 128 * p;
                const int r = c >> 2, sub = c & 3;
                cp_async16(dA + (uint32_t)(r * 80 + sub * 16),
                           Abase + (size_t)r * lda + kofs + sub * 8);
                cp_async16(dB + (uint32_t)(r * 80 + sub * 16),
                           Bbase + (size_t)r * ldb + kofs + sub * 8);
            }
        }
        asm volatile("cp.async.commit_group;" ::: "memory");
    };

    issue(0); issue(1);

    uint32_t acc[4][8][2];           // fp16x2 accumulators
#pragma unroll
    for (int mi = 0; mi < 4; mi++)
#pragma unroll
        for (int ni = 0; ni < 8; ni++) { acc[mi][ni][0] = 0u; acc[mi][ni][1] = 0u; }

    const int laneM = lane >> 3;
    const int laneR = lane & 7;
    uint32_t aoff[4], boff[4];
#pragma unroll
    for (int mi = 0; mi < 4; mi++) {
        const int row = warp_m * 64 + mi * 16 + (laneM & 1) * 8 + laneR;
        aoff[mi] = (uint32_t)(row * SROWH + (laneM >> 1) * 8) * 2u;
    }
#pragma unroll
    for (int pi = 0; pi < 4; pi++) {
        const int row = warp_n * 64 + pi * 16 + (laneM >> 1) * 8 + laneR;
        boff[pi] = (uint32_t)(row * SROWH + (laneM & 1) * 8) * 2u;
    }

    uint32_t afr[2][4][4];
    uint32_t bfr[2][4][4];

    for (int it = 0; it < niter; ++it) {
        asm volatile("cp.async.wait_group 1;" ::: "memory");
        __syncthreads();

        const int s = it % STAGES;
        const uint32_t sAu = smemA_u + s * T_STAGE_BYTES;
        const uint32_t sBu = smemB_u + s * T_STAGE_BYTES;

#pragma unroll
        for (int mi = 0; mi < 4; mi++) LDSM_X4(afr[0][mi], sAu + aoff[mi]);
#pragma unroll
        for (int pi = 0; pi < 4; pi++) LDSM_X4(bfr[0][pi], sBu + boff[pi]);

        issue(it + 2);

#pragma unroll
        for (int mi = 0; mi < 4; mi++) LDSM_X4(afr[1][mi], sAu + aoff[mi] + 32);
#pragma unroll
        for (int pi = 0; pi < 4; pi++) LDSM_X4(bfr[1][pi], sBu + boff[pi] + 32);

#pragma unroll
        for (int ks = 0; ks < 2; ks++)
#pragma unroll
            for (int mi = 0; mi < 4; mi++)
#pragma unroll
                for (int ni = 0; ni < 8; ni++)
                    mma_f16acc(acc[mi][ni], afr[ks][mi], &bfr[ks][ni >> 1][(ni & 1) * 2]);
    }

    // Epilogue: exp + staged coalesced store + atomic rowsums
    const int rrow = warp_m * 64 + (lane >> 2);
    const int rcol = warp_n * 64 + (lane & 3) * 2;
    __syncthreads();
    float* bsums = sums + (size_t)blockIdx.z * NSEQ + bm;
#pragma unroll
    for (int mi = 0; mi < 4; mi++) {
        float rs0 = 0.0f, rs1 = 0.0f;
#pragma unroll
        for (int ni = 0; ni < 8; ni++) {
            const int r0 = rrow + mi * 16;
            const int c  = rcol + ni * 8;
            float2 lo = __half22float2(*(const __half2*)&acc[mi][ni][0]);
            float2 hi = __half22float2(*(const __half2*)&acc[mi][ni][1]);
            float e0 = ex2f(fmaf(lo.x, alpha, -EXP_SHIFT_L2));
            float e1 = ex2f(fmaf(lo.y, alpha, -EXP_SHIFT_L2));
            float e2 = ex2f(fmaf(hi.x, alpha, -EXP_SHIFT_L2));
            float e3 = ex2f(fmaf(hi.y, alpha, -EXP_SHIFT_L2));
            rs0 += e0 + e1;
            rs1 += e2 + e3;
            *(__half2*)(hsmem + r0 * EROWH + c)       = __floats2half2_rn(e0, e1);
            *(__half2*)(hsmem + (r0 + 8) * EROWH + c) = __floats2half2_rn(e2, e3);
        }
        rs0 += __shfl_xor_sync(0xFFFFFFFFu, rs0, 1);
        rs0 += __shfl_xor_sync(0xFFFFFFFFu, rs0, 2);
        rs1 += __shfl_xor_sync(0xFFFFFFFFu, rs1, 1);
        rs1 += __shfl_xor_sync(0xFFFFFFFFu, rs1, 2);
        if ((lane & 3) == 0) {
            atomicAdd(bsums + rrow + mi * 16, rs0);
            atomicAdd(bsums + rrow + mi * 16 + 8, rs1);
        }
    }
    __syncthreads();
    __half* C = Cout + blockIdx.z * sC;
#pragma unroll
    for (int i = 0; i < 16; i++) {
        const int idx = i * 128 + tid;
        const int r = idx >> 4;
        const int ch = idx & 15;
        uint4 val = *(const uint4*)(hsmem + r * EROWH + ch * 8);
        *(uint4*)(C + (size_t)(bm + r) * ldc + bn + ch * 8) = val;
    }
}

// ---------------------------------------------------------------------------
// fp32 -> fp16 copy
// ---------------------------------------------------------------------------
__global__ __launch_bounds__(256)
void f2h_kernel(const float* __restrict__ src, __half* __restrict__ dst, size_t n4)
{
    const size_t stride = (size_t)gridDim.x * 256;
    for (size_t i = blockIdx.x * 256ull + threadIdx.x; i < n4; i += stride) {
        float4 v = ((const float4*)src)[i];
        ((__half2*)dst)[2 * i]     = __floats2half2_rn(v.x, v.y);
        ((__half2*)dst)[2 * i + 1] = __floats2half2_rn(v.z, v.w);
    }
}

// ---------------------------------------------------------------------------
// Zero the rowsum accumulators (re-run on every graph replay).
// ---------------------------------------------------------------------------
__global__ __launch_bounds__(256)
void zero_sums_kernel(float* __restrict__ sums)
{
    const int i = blockIdx.x * 256 + threadIdx.x;
    if (i < BATCH * NSEQ) sums[i] = 0.0f;
}

// ---------------------------------------------------------------------------
// Tiled transpose with dtype conversion: out[c, r] = in[r, c]
// ---------------------------------------------------------------------------
template <typename TIN, typename TOUT>
__global__ __launch_bounds__(256)
void transpose_t(const TIN* __restrict__ in, TOUT* __restrict__ out,
                 int ld_in, int ld_out, size_t sIn, size_t sOut)
{
    __shared__ float tile[32][33];
    in  += blockIdx.z * sIn;
    out += blockIdx.z * sOut;
    const int r0 = blockIdx.y * 32;
    const int c0 = blockIdx.x * 32;
    const int tx = threadIdx.x;
    const int ty = threadIdx.y;
#pragma unroll
    for (int i = 0; i < 32; i += 8)
        tile[ty + i][tx] = (float)in[(size_t)(r0 + ty + i) * ld_in + c0 + tx];
    __syncthreads();
#pragma unroll
    for (int i = 0; i < 32; i += 8)
        out[(size_t)(c0 + ty + i) * ld_out + r0 + tx] = (TOUT)tile[tx][ty + i];
}

// ---------------------------------------------------------------------------
extern "C" void kernel_launch(void* const* d_in, const int* in_sizes, int n_in,
                              void* d_out, int out_size)
{
    const float* x = (const float*)d_in[0];   // [4, 4096, 768]
    const float* W = (const float*)d_in[1];   // [768, 2304]
    const float* b = (const float*)d_in[2];   // [2304]
    float* out = (float*)d_out;               // [4, 4096, 768]

    __half *xh, *qkvh, *E, *Wth, *Vth;
    float *sums;
    cudaGetSymbolAddress((void**)&xh, g_xh);
    cudaGetSymbolAddress((void**)&qkvh, g_qkvh);
    cudaGetSymbolAddress((void**)&E, g_E);
    cudaGetSymbolAddress((void**)&sums, g_sums);
    cudaGetSymbolAddress((void**)&Wth, g_Wth);
    cudaGetSymbolAddress((void**)&Vth, g_Vth);

    cudaFuncSetAttribute(hgemm_nt<EPI_BIAS_HALF>, cudaFuncAttributeMaxDynamicSharedMemorySize, GEMM_DYNSMEM);
    cudaFuncSetAttribute(hgemm_nt<EPI_SCALE_F32>, cudaFuncAttributeMaxDynamicSharedMemorySize, GEMM_DYNSMEM);
    cudaFuncSetAttribute(hgemm_exp,               cudaFuncAttributeMaxDynamicSharedMemorySize, GEMM_DYNSMEM);

    const size_t qkvStride = (size_t)NSEQ * H3;
    const size_t sStride   = (size_t)NSEQ * NSEQ;
    const size_t oStride   = (size_t)NSEQ * DIMC;
    const size_t vtStride  = (size_t)DIMC * NSEQ;

    // 0a) xh = fp16(x);  0b) zero rowsum accumulators
    f2h_kernel<<<2048, 256>>>(x, xh, (size_t)BATCH * NSEQ * DIMC / 4);
    zero_sums_kernel<<<(BATCH * NSEQ + 255) / 256, 256>>>(sums);

    // 0c) Wth = fp16(W^T) : [768,2304] -> [2304,768]
    {
        dim3 grid(H3 / 32, DIMC / 32, 1);
        transpose_t<float, __half><<<grid, dim3(32, 8)>>>(W, Wth, H3, DIMC, 0, 0);
    }

    // 1) qkvh = fp16(xh @ Wth^T + b) : M=16384, N=2304, K=768  (f32 accum)
    {
        dim3 grid(H3 / 128, (BATCH * NSEQ) / 128, 1);
        hgemm_nt<EPI_BIAS_HALF><<<grid, 128, GEMM_DYNSMEM>>>(
            xh, Wth, b, nullptr, qkvh, DIMC, DIMC, DIMC, H3, 0, 0, 0, 1.0f);
    }

    // 2) Vth = V^T per batch : [4096,768] -> [768,4096]
    {
        dim3 grid(DIMC / 32, NSEQ / 32, BATCH);
        transpose_t<__half, __half><<<grid, dim3(32, 8)>>>(qkvh + 2 * DIMC, Vth, H3, NSEQ,
                                                           qkvStride, vtStride);
    }

    // 3) E = exp(Q @ K^T / sqrt(768) - 2) per batch, fp16 ACCUM (2x HMMA rate)
    {
        dim3 grid(NSEQ / 128, NSEQ / 128, BATCH);
        const float alpha = 1.4426950408889634f / sqrtf((float)DIMC);  // log2(e)/sqrt(H)
        hgemm_exp<<<grid, 128, GEMM_DYNSMEM>>>(
            qkvh, qkvh + DIMC, sums, E, DIMC, H3, H3, NSEQ,
            qkvStride, qkvStride, sStride, alpha);
    }

    // 4) out = diag(1/sums) * (E @ Vth^T) per batch (f32 accum, fp32 out)
    {
        dim3 grid(DIMC / 128, NSEQ / 128, BATCH);
        hgemm_nt<EPI_SCALE_F32><<<grid, 128, GEMM_DYNSMEM>>>(
            E, Vth, nullptr, sums, out, NSEQ, NSEQ, NSEQ, DIMC,
            sStride, vtStride, oStride, 1.0f);
    }
}

// round 17
// speedup vs baseline: 1.1130x; 1.0606x over previous
#include <cuda_runtime.h>
#include <cuda_fp16.h>
#include <math.h>
#include <stdint.h>

// ---------------------------------------------------------------------------
// Problem constants
// ---------------------------------------------------------------------------
static constexpr int BATCH = 4;
static constexpr int NSEQ  = 4096;
static constexpr int DIMC  = 768;       // input dim == head dim
static constexpr int H3    = 3 * DIMC;  // 2304

// Scratch
__device__ __half g_xh[(size_t)BATCH * NSEQ * DIMC];          // 25 MB
__device__ __half g_qkvh[(size_t)BATCH * NSEQ * H3];          // 75 MB
__device__ __half g_E[(size_t)BATCH * NSEQ * NSEQ];           // 134 MB (exp(scores), unnormalized)
__device__ float  g_sums[(size_t)BATCH * NSEQ];               // 64 KB  (rowsum of E, via atomics)
__device__ __half g_Wh[(size_t)DIMC * H3];                    // 3.5 MB (fp16 W, natural [768,2304])

// ---------------------------------------------------------------------------
// Helpers
// ---------------------------------------------------------------------------
__device__ __forceinline__ uint32_t smem_to_u32(const void* p) {
    uint32_t a;
    asm("{ .reg .u64 t; cvta.to.shared.u64 t, %1; cvt.u32.u64 %0, t; }"
        : "=r"(a) : "l"(p));
    return a;
}

__device__ __forceinline__ void cp_async16(uint32_t smem_addr, const void* gptr) {
    asm volatile("cp.async.cg.shared.global [%0], [%1], 16;"
                 :: "r"(smem_addr), "l"(gptr));
}

#define LDSM_X4(r, addr) \
    asm volatile("ldmatrix.sync.aligned.m8n8.x4.shared.b16 {%0,%1,%2,%3}, [%4];" \
                 : "=r"((r)[0]), "=r"((r)[1]), "=r"((r)[2]), "=r"((r)[3]) : "r"(addr))

#define LDSM_X4_T(r, addr) \
    asm volatile("ldmatrix.sync.aligned.m8n8.x4.trans.shared.b16 {%0,%1,%2,%3}, [%4];" \
                 : "=r"((r)[0]), "=r"((r)[1]), "=r"((r)[2]), "=r"((r)[3]) : "r"(addr))

__device__ __forceinline__ void mma_f16(float* d, const uint32_t* a, const uint32_t* b) {
    asm volatile(
        "mma.sync.aligned.m16n8k16.row.col.f32.f16.f16.f32 "
        "{%0,%1,%2,%3}, {%4,%5,%6,%7}, {%8,%9}, {%0,%1,%2,%3};"
        : "+f"(d[0]), "+f"(d[1]), "+f"(d[2]), "+f"(d[3])
        : "r"(a[0]), "r"(a[1]), "r"(a[2]), "r"(a[3]), "r"(b[0]), "r"(b[1]));
}

// fp16-accumulator variant (E-GEMM)
__device__ __forceinline__ void mma_f16acc(uint32_t* d, const uint32_t* a, const uint32_t* b) {
    asm volatile(
        "mma.sync.aligned.m16n8k16.row.col.f16.f16.f16.f16 "
        "{%0,%1}, {%2,%3,%4,%5}, {%6,%7}, {%0,%1};"
        : "+r"(d[0]), "+r"(d[1])
        : "r"(a[0]), "r"(a[1]), "r"(a[2]), "r"(a[3]), "r"(b[0]), "r"(b[1]));
}

__device__ __forceinline__ float ex2f(float t) {
    float r;
    asm("ex2.approx.f32 %0, %1;" : "=f"(r) : "f"(t));
    return r;
}

// Epilogue modes
static constexpr int EPI_BIAS_HALF = 0;   // += bias[N], write fp16 (QKV)
static constexpr int EPI_SCALE_F32 = 2;   // *= 1/sums[row], write fp32 (PV)

static constexpr float EXP_SHIFT_L2 = 2.8853900817779268f;   // 2 * log2(e)

// ---------------------------------------------------------------------------
// Tiling constants: block 128x128x32, 128 threads (4 warps 2x2, warp 64x64).
// A smem row 40 halfs (80B). Trans-B smem: [32 k-rows][136 n-halfs] (272B rows).
// ---------------------------------------------------------------------------
static constexpr int STAGES = 3;
static constexpr int SROWH = 40;                          // A: halfs per smem row
static constexpr int SROWB = 136;                         // trans-B: halfs per k-row
static constexpr int T_STAGE_BYTES = 128 * SROWH * 2;     // 10240 (A; also non-trans B)
static constexpr uint32_t GEMM_DYNSMEM =
    STAGES * 2u * (uint32_t)T_STAGE_BYTES;                // 61440 (trans-B tile 8704 <= 10240, padded)

// Staged-epilogue tile: 128 rows x 136 halfs
static constexpr int EROWH = 136;

// ---------------------------------------------------------------------------
// f32-accum GEMM with trans-B: C[M,N] = f( A[M,K] @ B[K,N] )
// A K-major [M,K]; B natural [K,N] (rows = k). 3-stage cp.async, 3 CTAs/SM.
// Grid: (N/128, M/128, batch).
// ---------------------------------------------------------------------------
template <int EPI>
__global__ __launch_bounds__(128, 3)
void hgemm_tn(const __half* __restrict__ A, const __half* __restrict__ B,
              const float* __restrict__ extra, float* __restrict__ sums,
              void* __restrict__ Cout,
              int K, int lda, int ldb, int ldc,
              size_t sA, size_t sB, size_t sC)
{
    extern __shared__ __half hsmem[];

    const int tid = threadIdx.x;
    const int lane = tid & 31;
    const int wid = tid >> 5;
    const int warp_m = wid & 1;
    const int warp_n = wid >> 1;
    const int bm = blockIdx.y * 128;
    const int bn = blockIdx.x * 128;

    const __half* Abase = A + blockIdx.z * sA + (size_t)bm * lda;
    const __half* Bbase = B + blockIdx.z * sB + bn;        // cols = n, rows = k

    const uint32_t smemA_u = smem_to_u32(hsmem);
    const uint32_t smemB_u = smemA_u + STAGES * T_STAGE_BYTES;

    const int niter = K >> 5;

    auto issue = [&](int it) {
        if (it < niter) {
            const int s = it % STAGES;
            const uint32_t dA = smemA_u + s * T_STAGE_BYTES;
            const uint32_t dB = smemB_u + s * T_STAGE_BYTES;
            const int kofs = it * 32;
#pragma unroll
            for (int p = 0; p < 4; p++) {
                const int c = tid + 128 * p;
                {   // A: 128 rows(m) x 32 halfs(k); 512 chunks
                    const int r = c >> 2, sub = c & 3;
                    cp_async16(dA + (uint32_t)(r * 80 + sub * 16),
                               Abase + (size_t)r * lda + kofs + sub * 8);
                }
                {   // B: 32 rows(k) x 128 halfs(n); 512 chunks
                    const int r = c >> 4, sub = c & 15;
                    cp_async16(dB + (uint32_t)(r * 272 + sub * 16),
                               Bbase + (size_t)(kofs + r) * ldb + sub * 8);
                }
            }
        }
        asm volatile("cp.async.commit_group;" ::: "memory");
    };

    issue(0); issue(1);

    float acc[4][8][4];
#pragma unroll
    for (int mi = 0; mi < 4; mi++)
#pragma unroll
        for (int ni = 0; ni < 8; ni++)
#pragma unroll
            for (int j = 0; j < 4; j++) acc[mi][ni][j] = 0.0f;

    const int laneM = lane >> 3;
    const int laneR = lane & 7;
    uint32_t aoff[4], boff[4];
#pragma unroll
    for (int mi = 0; mi < 4; mi++) {
        const int row = warp_m * 64 + mi * 16 + (laneM & 1) * 8 + laneR;
        aoff[mi] = (uint32_t)(row * SROWH + (laneM >> 1) * 8) * 2u;
    }
    // trans-B: matrix quad = (k0,n0),(k8,n0),(k0,n8),(k8,n8); lane row = k-row
#pragma unroll
    for (int pi = 0; pi < 4; pi++) {
        const int krow = (laneM & 1) * 8 + laneR;
        const int ncol = warp_n * 64 + pi * 16 + (laneM >> 1) * 8;
        boff[pi] = (uint32_t)(krow * SROWB + ncol) * 2u;
    }

    for (int it = 0; it < niter; ++it) {
        asm volatile("cp.async.wait_group 1;" ::: "memory");
        __syncthreads();
        issue(it + 2);

        const int s = it % STAGES;
        const uint32_t sAu = smemA_u + s * T_STAGE_BYTES;
        const uint32_t sBu = smemB_u + s * T_STAGE_BYTES;

#pragma unroll
        for (int ks = 0; ks < 2; ks++) {
            uint32_t afr[4][4];
            uint32_t bfr[4][4];
#pragma unroll
            for (int mi = 0; mi < 4; mi++) LDSM_X4(afr[mi], sAu + aoff[mi] + ks * 32);
#pragma unroll
            for (int pi = 0; pi < 4; pi++)
                LDSM_X4_T(bfr[pi], sBu + boff[pi] + ks * (16 * SROWB * 2));
#pragma unroll
            for (int mi = 0; mi < 4; mi++)
#pragma unroll
                for (int ni = 0; ni < 8; ni++)
                    mma_f16(acc[mi][ni], afr[mi], &bfr[ni >> 1][(ni & 1) * 2]);
        }
    }

    // Epilogue
    const int rrow = warp_m * 64 + (lane >> 2);
    const int rcol = warp_n * 64 + (lane & 3) * 2;
    const int erow = bm + rrow;
    const int ecol = bn + rcol;
#pragma unroll
    for (int mi = 0; mi < 4; mi++) {
        float s0 = 1.0f, s1 = 1.0f;
        if (EPI == EPI_SCALE_F32) {
            const float* bsums = sums + (size_t)blockIdx.z * NSEQ;
            s0 = __fdividef(1.0f, bsums[erow + mi * 16]);
            s1 = __fdividef(1.0f, bsums[erow + mi * 16 + 8]);
        }
#pragma unroll
        for (int ni = 0; ni < 8; ni++) {
            const int m0 = erow + mi * 16;
            const int n0 = ecol + ni * 8;
            float v0 = acc[mi][ni][0];
            float v1 = acc[mi][ni][1];
            float v2 = acc[mi][ni][2];
            float v3 = acc[mi][ni][3];
            if (EPI == EPI_BIAS_HALF) {
                const float b0 = extra[n0], b1 = extra[n0 + 1];
                v0 += b0; v1 += b1; v2 += b0; v3 += b1;
                __half* C = (__half*)Cout + blockIdx.z * sC;
                *(__half2*)(C + (size_t)m0 * ldc + n0)       = __floats2half2_rn(v0, v1);
                *(__half2*)(C + (size_t)(m0 + 8) * ldc + n0) = __floats2half2_rn(v2, v3);
            } else {  // EPI_SCALE_F32
                float* C = (float*)Cout + blockIdx.z * sC;
                *(float2*)(C + (size_t)m0 * ldc + n0)       = make_float2(v0 * s0, v1 * s0);
                *(float2*)(C + (size_t)(m0 + 8) * ldc + n0) = make_float2(v2 * s1, v3 * s1);
            }
        }
    }
}

// ---------------------------------------------------------------------------
// fp16-accum NT GEMM for E = exp(scores): unchanged from round 16.
// ---------------------------------------------------------------------------
__global__ __launch_bounds__(128, 3)
void hgemm_exp(const __half* __restrict__ A, const __half* __restrict__ B,
               float* __restrict__ sums, __half* __restrict__ Cout,
               int K, int lda, int ldb, int ldc,
               size_t sA, size_t sB, size_t sC, float alpha)
{
    extern __shared__ __half hsmem[];

    const int tid = threadIdx.x;
    const int lane = tid & 31;
    const int wid = tid >> 5;
    const int warp_m = wid & 1;
    const int warp_n = wid >> 1;
    const int bm = blockIdx.y * 128;
    const int bn = blockIdx.x * 128;

    const __half* Abase = A + blockIdx.z * sA + (size_t)bm * lda;
    const __half* Bbase = B + blockIdx.z * sB + (size_t)bn * ldb;

    const uint32_t smemA_u = smem_to_u32(hsmem);
    const uint32_t smemB_u = smemA_u + STAGES * T_STAGE_BYTES;

    const int niter = K >> 5;

    auto issue = [&](int it) {
        if (it < niter) {
            const int s = it % STAGES;
            const uint32_t dA = smemA_u + s * T_STAGE_BYTES;
            const uint32_t dB = smemB_u + s * T_STAGE_BYTES;
            const int kofs = it * 32;
#pragma unroll
            for (int p = 0; p < 4; p++) {
                const int c = tid + 128 * p;
                const int r = c >> 2, sub = c & 3;
                cp_async16(dA + (uint32_t)(r * 80 + sub * 16),
                           Abase + (size_t)r * lda + kofs + sub * 8);
                cp_async16(dB + (uint32_t)(r * 80 + sub * 16),
                           Bbase + (size_t)r * ldb + kofs + sub * 8);
            }
        }
        asm volatile("cp.async.commit_group;" ::: "memory");
    };

    issue(0); issue(1);

    uint32_t acc[4][8][2];
#pragma unroll
    for (int mi = 0; mi < 4; mi++)
#pragma unroll
        for (int ni = 0; ni < 8; ni++) { acc[mi][ni][0] = 0u; acc[mi][ni][1] = 0u; }

    const int laneM = lane >> 3;
    const int laneR = lane & 7;
    uint32_t aoff[4], boff[4];
#pragma unroll
    for (int mi = 0; mi < 4; mi++) {
        const int row = warp_m * 64 + mi * 16 + (laneM & 1) * 8 + laneR;
        aoff[mi] = (uint32_t)(row * SROWH + (laneM >> 1) * 8) * 2u;
    }
#pragma unroll
    for (int pi = 0; pi < 4; pi++) {
        const int row = warp_n * 64 + pi * 16 + (laneM >> 1) * 8 + laneR;
        boff[pi] = (uint32_t)(row * SROWH + (laneM & 1) * 8) * 2u;
    }

    uint32_t afr[2][4][4];
    uint32_t bfr[2][4][4];

    for (int it = 0; it < niter; ++it) {
        asm volatile("cp.async.wait_group 1;" ::: "memory");
        __syncthreads();

        const int s = it % STAGES;
        const uint32_t sAu = smemA_u + s * T_STAGE_BYTES;
        const uint32_t sBu = smemB_u + s * T_STAGE_BYTES;

#pragma unroll
        for (int mi = 0; mi < 4; mi++) LDSM_X4(afr[0][mi], sAu + aoff[mi]);
#pragma unroll
        for (int pi = 0; pi < 4; pi++) LDSM_X4(bfr[0][pi], sBu + boff[pi]);

        issue(it + 2);

#pragma unroll
        for (int mi = 0; mi < 4; mi++) LDSM_X4(afr[1][mi], sAu + aoff[mi] + 32);
#pragma unroll
        for (int pi = 0; pi < 4; pi++) LDSM_X4(bfr[1][pi], sBu + boff[pi] + 32);

#pragma unroll
        for (int ks = 0; ks < 2; ks++)
#pragma unroll
            for (int mi = 0; mi < 4; mi++)
#pragma unroll
                for (int ni = 0; ni < 8; ni++)
                    mma_f16acc(acc[mi][ni], afr[ks][mi], &bfr[ks][ni >> 1][(ni & 1) * 2]);
    }

    // Epilogue: exp + staged coalesced store + atomic rowsums
    const int rrow = warp_m * 64 + (lane >> 2);
    const int rcol = warp_n * 64 + (lane & 3) * 2;
    __syncthreads();
    float* bsums = sums + (size_t)blockIdx.z * NSEQ + bm;
#pragma unroll
    for (int mi = 0; mi < 4; mi++) {
        float rs0 = 0.0f, rs1 = 0.0f;
#pragma unroll
        for (int ni = 0; ni < 8; ni++) {
            const int r0 = rrow + mi * 16;
            const int c  = rcol + ni * 8;
            float2 lo = __half22float2(*(const __half2*)&acc[mi][ni][0]);
            float2 hi = __half22float2(*(const __half2*)&acc[mi][ni][1]);
            float e0 = ex2f(fmaf(lo.x, alpha, -EXP_SHIFT_L2));
            float e1 = ex2f(fmaf(lo.y, alpha, -EXP_SHIFT_L2));
            float e2 = ex2f(fmaf(hi.x, alpha, -EXP_SHIFT_L2));
            float e3 = ex2f(fmaf(hi.y, alpha, -EXP_SHIFT_L2));
            rs0 += e0 + e1;
            rs1 += e2 + e3;
            *(__half2*)(hsmem + r0 * EROWH + c)       = __floats2half2_rn(e0, e1);
            *(__half2*)(hsmem + (r0 + 8) * EROWH + c) = __floats2half2_rn(e2, e3);
        }
        rs0 += __shfl_xor_sync(0xFFFFFFFFu, rs0, 1);
        rs0 += __shfl_xor_sync(0xFFFFFFFFu, rs0, 2);
        rs1 += __shfl_xor_sync(0xFFFFFFFFu, rs1, 1);
        rs1 += __shfl_xor_sync(0xFFFFFFFFu, rs1, 2);
        if ((lane & 3) == 0) {
            atomicAdd(bsums + rrow + mi * 16, rs0);
            atomicAdd(bsums + rrow + mi * 16 + 8, rs1);
        }
    }
    __syncthreads();
    __half* C = Cout + blockIdx.z * sC;
#pragma unroll
    for (int i = 0; i < 16; i++) {
        const int idx = i * 128 + tid;
        const int r = idx >> 4;
        const int ch = idx & 15;
        uint4 val = *(const uint4*)(hsmem + r * EROWH + ch * 8);
        *(uint4*)(C + (size_t)(bm + r) * ldc + bn + ch * 8) = val;
    }
}

// ---------------------------------------------------------------------------
// fp32 -> fp16 copy
// ---------------------------------------------------------------------------
__global__ __launch_bounds__(256)
void f2h_kernel(const float* __restrict__ src, __half* __restrict__ dst, size_t n4)
{
    const size_t stride = (size_t)gridDim.x * 256;
    for (size_t i = blockIdx.x * 256ull + threadIdx.x; i < n4; i += stride) {
        float4 v = ((const float4*)src)[i];
        ((__half2*)dst)[2 * i]     = __floats2half2_rn(v.x, v.y);
        ((__half2*)dst)[2 * i + 1] = __floats2half2_rn(v.z, v.w);
    }
}

// ---------------------------------------------------------------------------
// Zero the rowsum accumulators (re-run on every graph replay).
// ---------------------------------------------------------------------------
__global__ __launch_bounds__(256)
void zero_sums_kernel(float* __restrict__ sums)
{
    const int i = blockIdx.x * 256 + threadIdx.x;
    if (i < BATCH * NSEQ) sums[i] = 0.0f;
}

// ---------------------------------------------------------------------------
extern "C" void kernel_launch(void* const* d_in, const int* in_sizes, int n_in,
                              void* d_out, int out_size)
{
    const float* x = (const float*)d_in[0];   // [4, 4096, 768]
    const float* W = (const float*)d_in[1];   // [768, 2304]
    const float* b = (const float*)d_in[2];   // [2304]
    float* out = (float*)d_out;               // [4, 4096, 768]

    __half *xh, *qkvh, *E, *Wh;
    float *sums;
    cudaGetSymbolAddress((void**)&xh, g_xh);
    cudaGetSymbolAddress((void**)&qkvh, g_qkvh);
    cudaGetSymbolAddress((void**)&E, g_E);
    cudaGetSymbolAddress((void**)&sums, g_sums);
    cudaGetSymbolAddress((void**)&Wh, g_Wh);

    cudaFuncSetAttribute(hgemm_tn<EPI_BIAS_HALF>, cudaFuncAttributeMaxDynamicSharedMemorySize, GEMM_DYNSMEM);
    cudaFuncSetAttribute(hgemm_tn<EPI_SCALE_F32>, cudaFuncAttributeMaxDynamicSharedMemorySize, GEMM_DYNSMEM);
    cudaFuncSetAttribute(hgemm_exp,               cudaFuncAttributeMaxDynamicSharedMemorySize, GEMM_DYNSMEM);

    const size_t qkvStride = (size_t)NSEQ * H3;
    const size_t sStride   = (size_t)NSEQ * NSEQ;
    const size_t oStride   = (size_t)NSEQ * DIMC;

    // 0) xh = fp16(x); Wh = fp16(W) (natural layout); zero rowsums
    f2h_kernel<<<2048, 256>>>(x, xh, (size_t)BATCH * NSEQ * DIMC / 4);
    f2h_kernel<<<432, 256>>>(W, Wh, (size_t)DIMC * H3 / 4);
    zero_sums_kernel<<<(BATCH * NSEQ + 255) / 256, 256>>>(sums);

    // 1) qkvh = fp16(xh @ W + b) : TN, M=16384, N=2304, K=768
    {
        dim3 grid(H3 / 128, (BATCH * NSEQ) / 128, 1);
        hgemm_tn<EPI_BIAS_HALF><<<grid, 128, GEMM_DYNSMEM>>>(
            xh, Wh, b, nullptr, qkvh, DIMC, DIMC, H3, H3, 0, 0, 0);
    }

    // 2) E = exp(Q @ K^T / sqrt(768) - 2) per batch, fp16 accum + atomic rowsums
    {
        dim3 grid(NSEQ / 128, NSEQ / 128, BATCH);
        const float alpha = 1.4426950408889634f / sqrtf((float)DIMC);  // log2(e)/sqrt(H)
        hgemm_exp<<<grid, 128, GEMM_DYNSMEM>>>(
            qkvh, qkvh + DIMC, sums, E, DIMC, H3, H3, NSEQ,
            qkvStride, qkvStride, sStride, alpha);
    }

    // 3) out = diag(1/sums) * (E @ V) : TN per batch, V = qkvh[:, 1536:2304] rows=seq
    {
        dim3 grid(DIMC / 128, NSEQ / 128, BATCH);
        hgemm_tn<EPI_SCALE_F32><<<grid, 128, GEMM_DYNSMEM>>>(
            E, qkvh + 2 * DIMC, nullptr, sums, out, NSEQ, NSEQ, H3, DIMC,
            sStride, qkvStride, oStride);
    }
}